// round 8
// baseline (speedup 1.0000x reference)
#include <cuda_runtime.h>
#include <cstdint>
#include <cstddef>

#define NPTS 4096
#define DIM  64
#define NBLK 128     // persistent blocks (<=148 SMs, 1 block/SM -> co-resident)
#define TPB  1024
#define KNN  8       // per-lane candidate list length

// ---------------------------------------------------------------------------
// Scratch (allocation-free rule: __device__ globals)
// ---------------------------------------------------------------------------
__device__ float g_sq[NPTS];
__device__ float g_d2[(size_t)NPTS * NPTS];          // 64 MB f32, L2-resident
__device__ float g_len[NPTS];                        // MST edge lengths
__device__ unsigned long long g_knn[(size_t)NPTS * 32 * KNN];  // 8 MB lists
__device__ unsigned long long g_best[3][NPTS];       // triple-buffered best keys
__device__ int          g_bar_cnt;
__device__ volatile int g_bar_gen;

static __device__ __forceinline__ float inf32() { return __int_as_float(0x7f800000); }
static __device__ __forceinline__ unsigned long long umin64(unsigned long long a,
                                                            unsigned long long b) {
    return a < b ? a : b;
}
// global key = (f32 d2 bits << 24) | (min(u,v)<<12) | max(u,v)
// globally unique; identical from both endpoints => only mutual 2-cycles.
static __device__ __forceinline__ unsigned long long mkkey(unsigned wbits,
                                                           unsigned a, unsigned b) {
    unsigned lo = min(a, b), hi = max(a, b);
    return ((unsigned long long)wbits << 24) | (lo << 12) | hi;
}

static __device__ __forceinline__ void gridbar() {
    __syncthreads();
    if (threadIdx.x == 0) {
        __threadfence();
        int gen = g_bar_gen;
        if (atomicAdd(&g_bar_cnt, 1) == NBLK - 1) {
            g_bar_cnt = 0;
            __threadfence();
            g_bar_gen = gen + 1;
        } else {
            while (g_bar_gen == gen) { }
        }
        __threadfence();
    }
    __syncthreads();
}

// ---------------------------------------------------------------------------
// Kernel 1: warp-per-row squared norms + clear best buffers + barrier reset
// ---------------------------------------------------------------------------
__global__ void k_init(const float* __restrict__ p) {
    const int t   = threadIdx.x;
    const int gt  = blockIdx.x * TPB + t;
    const int row = gt >> 5;
    const int ln  = gt & 31;

    if (gt == 0) { g_bar_cnt = 0; g_bar_gen = 0; }
    if (gt < 3 * NPTS) ((unsigned long long*)g_best)[gt] = ~0ull;

    float2 v = *(const float2*)(p + (size_t)row * DIM + ln * 2);
    float acc = fmaf(v.x, v.x, v.y * v.y);
#pragma unroll
    for (int s = 16; s > 0; s >>= 1)
        acc += __shfl_down_sync(0xFFFFFFFFu, acc, s);
    if (ln == 0) g_sq[row] = acc;
}

// ---------------------------------------------------------------------------
// Kernel 2: f32 d2 matrix (128x128 tile, 8x8/thread, packed f32x2 FMA) with
// fused Boruvka round-0 min-edge epilogue (singleton comps -> plain row min).
// ---------------------------------------------------------------------------
__global__ void k_d2(const float* __restrict__ p) {
    __shared__ float As[32][128];
    __shared__ float Bs[32][128];

    const int t  = threadIdx.x;          // 0..255
    const int tx = t & 15;
    const int ty = t >> 4;
    const int i0 = blockIdx.y * 128;
    const int j0 = blockIdx.x * 128;

    const int lr = t >> 1;
    const int lc = (t & 1) * 16;

    unsigned long long acc2[8][4];
#pragma unroll
    for (int m = 0; m < 8; m++)
#pragma unroll
        for (int n = 0; n < 4; n++) acc2[m][n] = 0ull;

#pragma unroll
    for (int k0 = 0; k0 < DIM; k0 += 32) {
#pragma unroll
        for (int q = 0; q < 4; q++) {
            int c = lc + q * 4;
            float4 va = *(const float4*)(p + (size_t)(i0 + lr) * DIM + k0 + c);
            As[c + 0][lr] = va.x; As[c + 1][lr] = va.y;
            As[c + 2][lr] = va.z; As[c + 3][lr] = va.w;
            float4 vb = *(const float4*)(p + (size_t)(j0 + lr) * DIM + k0 + c);
            Bs[c + 0][lr] = vb.x; Bs[c + 1][lr] = vb.y;
            Bs[c + 2][lr] = vb.z; Bs[c + 3][lr] = vb.w;
        }
        __syncthreads();

#pragma unroll
        for (int k = 0; k < 32; k++) {
            uint4 a0 = *(const uint4*)&As[k][ty * 8];
            uint4 a1 = *(const uint4*)&As[k][ty * 8 + 4];
            unsigned au[8] = {a0.x, a0.y, a0.z, a0.w, a1.x, a1.y, a1.z, a1.w};
            ulonglong2 b0 = *(const ulonglong2*)&Bs[k][tx * 8];
            ulonglong2 b1 = *(const ulonglong2*)&Bs[k][tx * 8 + 4];
            unsigned long long bp[4] = {b0.x, b0.y, b1.x, b1.y};
#pragma unroll
            for (int m = 0; m < 8; m++) {
                unsigned long long ap;
                asm("mov.b64 %0, {%1, %1};" : "=l"(ap) : "r"(au[m]));
#pragma unroll
                for (int n = 0; n < 4; n++)
                    asm("fma.rn.f32x2 %0, %1, %2, %0;"
                        : "+l"(acc2[m][n]) : "l"(ap), "l"(bp[n]));
            }
        }
        __syncthreads();
    }

    float sqi[8], sqj[8];
#pragma unroll
    for (int m = 0; m < 8; m++) sqi[m] = g_sq[i0 + ty * 8 + m];
#pragma unroll
    for (int n = 0; n < 8; n++) sqj[n] = g_sq[j0 + tx * 8 + n];

#pragma unroll
    for (int m = 0; m < 8; m++) {
        const int row = i0 + ty * 8 + m;
        float o[8];
#pragma unroll
        for (int n = 0; n < 4; n++) {
            unsigned lo, hi;
            asm("mov.b64 {%0, %1}, %2;" : "=r"(lo), "=r"(hi) : "l"(acc2[m][n]));
            float d0 = __uint_as_float(lo), d1 = __uint_as_float(hi);
            o[2 * n + 0] = fmaxf(sqi[m] + sqj[2 * n + 0] - 2.f * d0, 0.f);
            o[2 * n + 1] = fmaxf(sqi[m] + sqj[2 * n + 1] - 2.f * d1, 0.f);
        }
        float* dst = g_d2 + (size_t)row * NPTS + j0 + tx * 8;
        *(float4*)(dst)     = *(float4*)(o);
        *(float4*)(dst + 4) = *(float4*)(o + 4);

        // fused round-0 min-edge
        unsigned long long key = ~0ull;
#pragma unroll
        for (int n = 0; n < 8; n++) {
            unsigned jj = (unsigned)(j0 + tx * 8 + n);
            if (jj != (unsigned)row)
                key = umin64(key, mkkey(__float_as_uint(o[n]), (unsigned)row, jj));
        }
#pragma unroll
        for (int s = 8; s > 0; s >>= 1)
            key = umin64(key, __shfl_down_sync(0xFFFFFFFFu, key, s, 16));
        if (tx == 0) atomicMin(&g_best[0][row], key);
    }
}

// ---------------------------------------------------------------------------
// Kernel 3: per-lane 8-NN lists (branchless maintenance).
// Warp per row; lane handles cols lane+32s. Local key = (wbits<<32)|j,
// ascending sorted. Cheap u32 guard; insert = 8-step branchless bubble.
// Layout: g_knn[row*256 + k*32 + lane] -> coalesced round-time reads.
// ---------------------------------------------------------------------------
__global__ void k_knn() {
    const int t    = threadIdx.x;            // 256
    const int wid  = t >> 5;
    const int lane = t & 31;
    const int row  = blockIdx.x * 8 + wid;

    const float* r = g_d2 + (size_t)row * NPTS;
    unsigned long long list[KNN];
#pragma unroll
    for (int i = 0; i < KNN; i++) list[i] = ~0ull;

#pragma unroll 4
    for (int s = 0; s < 128; s++) {
        const int j = s * 32 + lane;
        unsigned wb = __float_as_uint(__ldg(r + j));
        if (j == row) wb = 0xFFFFFFFFu;
        if (wb < (unsigned)(list[KNN - 1] >> 32)) {
            unsigned long long key = ((unsigned long long)wb << 32) | (unsigned)j;
#pragma unroll
            for (int i = 0; i < KNN; i++) {
                unsigned long long mn = key < list[i] ? key : list[i];
                unsigned long long mx = key < list[i] ? list[i] : key;
                list[i] = mn;
                key     = mx;
            }
        }
    }
#pragma unroll
    for (int k = 0; k < KNN; k++)
        g_knn[(size_t)row * (32 * KNN) + k * 32 + lane] = list[k];
}

// ---------------------------------------------------------------------------
// Kernel 4: persistent Boruvka + sort. Rounds >=1 scan kNN lists; a lane
// whose 8 entries are all in-component rescans its 128-element slice of the
// exact f32 row (rare fallback keeps selection exact). One barrier per round;
// all blocks hook redundantly in their own shared memory.
// ---------------------------------------------------------------------------
__global__ void __launch_bounds__(TPB, 1) k_mst(float* __restrict__ out) {
    __shared__ unsigned short comp[NPTS];   // 8 KB persistent labels
    __shared__ int par[NPTS];               // 16 KB; reused as float sort buf
    __shared__ int s_m;                     // root (new component) count
    __shared__ int s_cnt;                   // block0 edge counter

    const int t    = threadIdx.x;
    const int wid  = t >> 5;
    const int lane = t & 31;
    const int row  = blockIdx.x * 32 + wid;

    for (int i = t; i < NPTS; i += TPB) comp[i] = (unsigned short)i;
    if (t == 0) s_cnt = 0;
    __syncthreads();

    for (int k = 0; k < 12; k++) {
        if (k > 0) {
            const unsigned myc = comp[row];
            const unsigned long long* lst = g_knn + (size_t)row * (32 * KNN);

            unsigned long long best = ~0ull;
            bool ok = false;
#pragma unroll
            for (int q = 0; q < KNN; q++) {
                unsigned long long e = lst[q * 32 + lane];
                if (!ok && e != ~0ull) {
                    unsigned j = (unsigned)(e & 0xFFFFu);
                    if (comp[j] != myc) {
                        best = mkkey((unsigned)(e >> 32), (unsigned)row, j);
                        ok = true;
                    }
                }
            }
            if (!ok) {
                // exact fallback: rescan this lane's 128 elements
                const float* r = g_d2 + (size_t)row * NPTS;
                for (int s = 0; s < 128; s++) {
                    const int j = s * 32 + lane;
                    if (comp[j] != myc)
                        best = umin64(best, mkkey(__float_as_uint(r[j]),
                                                  (unsigned)row, (unsigned)j));
                }
            }
#pragma unroll
            for (int s = 16; s > 0; s >>= 1)
                best = umin64(best, __shfl_down_sync(0xFFFFFFFFu, best, s));
            if (lane == 0 && best != ~0ull)
                atomicMin(&g_best[k % 3][myc], best);

            gridbar();
        }

        // ---- hook (all blocks, redundant & deterministic) ----
        const unsigned long long* B = g_best[k % 3];
        for (int c = t; c < NPTS; c += TPB) par[c] = c;
        if (t == 0) s_m = 0;
        __syncthreads();

        int local_roots = 0;
        for (int c = t; c < NPTS; c += TPB) {
            unsigned long long key = B[c];
            if (key != ~0ull) {
                unsigned id = (unsigned)(key & 0xFFFFFFu);
                int u = (int)(id >> 12), v = (int)(id & 0xFFFu);
                int cu = comp[u], cv = comp[v];
                int other = (cu == c) ? cv : cu;
                bool mutual = (B[other] == key);
                if (!mutual)        par[c] = other;
                else if (c > other) par[c] = other;
                else                local_roots++;
                if (blockIdx.x == 0 && (!mutual || c < other)) {
                    int idx = atomicAdd(&s_cnt, 1);
                    float w2 = __uint_as_float((unsigned)((key >> 24) & 0xFFFFFFFFull));
                    g_len[idx] = sqrtf(w2);
                }
            }
        }
#pragma unroll
        for (int s = 16; s > 0; s >>= 1)
            local_roots += __shfl_down_sync(0xFFFFFFFFu, local_roots, s);
        if (lane == 0 && local_roots) atomicAdd(&s_m, local_roots);
        __syncthreads();

        // pointer jumping with convergence early-exit
        for (int it = 0; it < 12; it++) {
            int chg = 0;
            for (int c = t; c < NPTS; c += TPB) {
                int p1 = par[c];
                int p2 = par[p1];
                if (p2 != p1) { par[c] = p2; chg = 1; }
            }
            if (!__syncthreads_or(chg)) break;
        }

        for (int i = t; i < NPTS; i += TPB)
            comp[i] = (unsigned short)par[comp[i]];
        if (t < 32) g_best[(k + 2) % 3][blockIdx.x * 32 + t] = ~0ull;
        __syncthreads();

        if (s_m <= 1) break;
    }

    // ---- block 0: bitonic sort (pad one +inf), write output ----
    if (blockIdx.x != 0) return;
    __syncthreads();
    float* sh = (float*)par;
    for (int m = t; m < NPTS; m += TPB)
        sh[m] = (m < NPTS - 1) ? g_len[m] : inf32();
    __syncthreads();

    for (int kk = 2; kk <= NPTS; kk <<= 1) {
        for (int j = kk >> 1; j > 0; j >>= 1) {
#pragma unroll
            for (int tt = 0; tt < 2; tt++) {
                int u = t + tt * TPB;
                int i = ((u & ~(j - 1)) << 1) | (u & (j - 1));
                int l = i | j;
                float a = sh[i], c = sh[l];
                bool up = (i & kk) == 0;
                if ((a > c) == up) { sh[i] = c; sh[l] = a; }
            }
            __syncthreads();
        }
    }
    for (int m = t; m < NPTS - 1; m += TPB) out[m] = sh[m];
}

// ---------------------------------------------------------------------------
extern "C" void kernel_launch(void* const* d_in, const int* in_sizes, int n_in,
                              void* d_out, int out_size) {
    (void)in_sizes; (void)n_in; (void)out_size;
    const float* points = (const float*)d_in[0];
    float* out = (float*)d_out;

    k_init<<<NPTS * 32 / TPB, TPB>>>(points);            // 128 x 1024
    k_d2<<<dim3(NPTS / 128, NPTS / 128), 256>>>(points); // 32x32 x 256
    k_knn<<<NPTS / 8, 256>>>();                          // 512 x 256
    k_mst<<<NBLK, TPB>>>(out);
}

// round 9
// speedup vs baseline: 1.6117x; 1.6117x over previous
#include <cuda_runtime.h>
#include <cstdint>
#include <cstddef>

#define NPTS 4096
#define DIM  64
#define NBLK 128     // persistent blocks (<=148 SMs, 1 block/SM -> co-resident)
#define TPB  1024

// ---------------------------------------------------------------------------
// Scratch (allocation-free rule: __device__ globals)
// ---------------------------------------------------------------------------
__device__ float g_sq[NPTS];
__device__ float g_d2[(size_t)NPTS * NPTS];          // 64 MB f32, L2-resident
__device__ float g_len[NPTS];                        // MST edge lengths
__device__ unsigned long long g_cache[NPTS];         // per-row best edge (w<<32|j)
__device__ unsigned long long g_best[3][NPTS];       // triple-buffered comp keys
__device__ int          g_bar_cnt;
__device__ volatile int g_bar_gen;

static __device__ __forceinline__ float inf32() { return __int_as_float(0x7f800000); }
static __device__ __forceinline__ unsigned long long umin64(unsigned long long a,
                                                            unsigned long long b) {
    return a < b ? a : b;
}
// global key = (f32 d2 bits << 24) | (min(u,v)<<12) | max(u,v)
// globally unique; identical from both endpoints => only mutual 2-cycles.
static __device__ __forceinline__ unsigned long long mkkey(unsigned wbits,
                                                           unsigned a, unsigned b) {
    unsigned lo = min(a, b), hi = max(a, b);
    return ((unsigned long long)wbits << 24) | (lo << 12) | hi;
}
// convert per-row cache entry (w<<32|j) for row c into the global key
static __device__ __forceinline__ unsigned long long cache2key(unsigned long long ck,
                                                               unsigned c) {
    if (ck == ~0ull) return ~0ull;
    return mkkey((unsigned)(ck >> 32), c, (unsigned)(ck & 0xFFFFu));
}

static __device__ __forceinline__ void gridbar() {
    __syncthreads();
    if (threadIdx.x == 0) {
        __threadfence();
        int gen = g_bar_gen;
        if (atomicAdd(&g_bar_cnt, 1) == NBLK - 1) {
            g_bar_cnt = 0;
            __threadfence();
            g_bar_gen = gen + 1;
        } else {
            while (g_bar_gen == gen) { }
        }
        __threadfence();
    }
    __syncthreads();
}

// ---------------------------------------------------------------------------
// Kernel 1: warp-per-row squared norms + clear cache/best + barrier reset
// ---------------------------------------------------------------------------
__global__ void k_init(const float* __restrict__ p) {
    const int t   = threadIdx.x;
    const int gt  = blockIdx.x * TPB + t;
    const int row = gt >> 5;
    const int ln  = gt & 31;

    if (gt == 0) { g_bar_cnt = 0; g_bar_gen = 0; }
    if (gt < 3 * NPTS) ((unsigned long long*)g_best)[gt] = ~0ull;
    if (gt < NPTS) g_cache[gt] = ~0ull;

    float2 v = *(const float2*)(p + (size_t)row * DIM + ln * 2);
    float acc = fmaf(v.x, v.x, v.y * v.y);
#pragma unroll
    for (int s = 16; s > 0; s >>= 1)
        acc += __shfl_down_sync(0xFFFFFFFFu, acc, s);
    if (ln == 0) g_sq[row] = acc;
}

// ---------------------------------------------------------------------------
// Kernel 2: f32 d2 matrix (128x128 tile, 8x8/thread, packed f32x2 FMA) with
// fused per-row best-edge epilogue -> atomicMin g_cache[row] = (wbits<<32)|j.
// (min by weight, then by smaller j == smaller canonical edge id.)
// ---------------------------------------------------------------------------
__global__ void k_d2(const float* __restrict__ p) {
    __shared__ float As[32][128];
    __shared__ float Bs[32][128];

    const int t  = threadIdx.x;          // 0..255
    const int tx = t & 15;
    const int ty = t >> 4;
    const int i0 = blockIdx.y * 128;
    const int j0 = blockIdx.x * 128;

    const int lr = t >> 1;
    const int lc = (t & 1) * 16;

    unsigned long long acc2[8][4];
#pragma unroll
    for (int m = 0; m < 8; m++)
#pragma unroll
        for (int n = 0; n < 4; n++) acc2[m][n] = 0ull;

#pragma unroll
    for (int k0 = 0; k0 < DIM; k0 += 32) {
#pragma unroll
        for (int q = 0; q < 4; q++) {
            int c = lc + q * 4;
            float4 va = *(const float4*)(p + (size_t)(i0 + lr) * DIM + k0 + c);
            As[c + 0][lr] = va.x; As[c + 1][lr] = va.y;
            As[c + 2][lr] = va.z; As[c + 3][lr] = va.w;
            float4 vb = *(const float4*)(p + (size_t)(j0 + lr) * DIM + k0 + c);
            Bs[c + 0][lr] = vb.x; Bs[c + 1][lr] = vb.y;
            Bs[c + 2][lr] = vb.z; Bs[c + 3][lr] = vb.w;
        }
        __syncthreads();

#pragma unroll
        for (int k = 0; k < 32; k++) {
            uint4 a0 = *(const uint4*)&As[k][ty * 8];
            uint4 a1 = *(const uint4*)&As[k][ty * 8 + 4];
            unsigned au[8] = {a0.x, a0.y, a0.z, a0.w, a1.x, a1.y, a1.z, a1.w};
            ulonglong2 b0 = *(const ulonglong2*)&Bs[k][tx * 8];
            ulonglong2 b1 = *(const ulonglong2*)&Bs[k][tx * 8 + 4];
            unsigned long long bp[4] = {b0.x, b0.y, b1.x, b1.y};
#pragma unroll
            for (int m = 0; m < 8; m++) {
                unsigned long long ap;
                asm("mov.b64 %0, {%1, %1};" : "=l"(ap) : "r"(au[m]));
#pragma unroll
                for (int n = 0; n < 4; n++)
                    asm("fma.rn.f32x2 %0, %1, %2, %0;"
                        : "+l"(acc2[m][n]) : "l"(ap), "l"(bp[n]));
            }
        }
        __syncthreads();
    }

    float sqi[8], sqj[8];
#pragma unroll
    for (int m = 0; m < 8; m++) sqi[m] = g_sq[i0 + ty * 8 + m];
#pragma unroll
    for (int n = 0; n < 8; n++) sqj[n] = g_sq[j0 + tx * 8 + n];

#pragma unroll
    for (int m = 0; m < 8; m++) {
        const int row = i0 + ty * 8 + m;
        float o[8];
#pragma unroll
        for (int n = 0; n < 4; n++) {
            unsigned lo, hi;
            asm("mov.b64 {%0, %1}, %2;" : "=r"(lo), "=r"(hi) : "l"(acc2[m][n]));
            float d0 = __uint_as_float(lo), d1 = __uint_as_float(hi);
            o[2 * n + 0] = fmaxf(sqi[m] + sqj[2 * n + 0] - 2.f * d0, 0.f);
            o[2 * n + 1] = fmaxf(sqi[m] + sqj[2 * n + 1] - 2.f * d1, 0.f);
        }
        float* dst = g_d2 + (size_t)row * NPTS + j0 + tx * 8;
        *(float4*)(dst)     = *(float4*)(o);
        *(float4*)(dst + 4) = *(float4*)(o + 4);

        // fused per-row best (w<<32|j)
        unsigned long long key = ~0ull;
#pragma unroll
        for (int n = 0; n < 8; n++) {
            unsigned jj = (unsigned)(j0 + tx * 8 + n);
            if (jj != (unsigned)row)
                key = umin64(key, ((unsigned long long)__float_as_uint(o[n]) << 32) | jj);
        }
#pragma unroll
        for (int s = 8; s > 0; s >>= 1)
            key = umin64(key, __shfl_down_sync(0xFFFFFFFFu, key, s, 16));
        if (tx == 0) atomicMin(&g_cache[row], key);
    }
}

// ---------------------------------------------------------------------------
// Kernel 3: persistent Boruvka + sort.
// Round 0 hooks directly off g_cache (no scan). Rounds >=1: a warp's cached
// best edge is reused while its partner is out-of-component (exact); else
// full row rescan refreshes the cache. One grid barrier per round.
// Hook runs redundantly in each block over the ACTIVE component list only.
// ---------------------------------------------------------------------------
__global__ void __launch_bounds__(TPB, 1) k_mst(float* __restrict__ out) {
    __shared__ unsigned short comp[NPTS];     // 8 KB persistent labels
    __shared__ int par[NPTS];                 // 16 KB; reused as float sort buf
    __shared__ unsigned short act[2][NPTS];   // 16 KB ping-pong active comps
    __shared__ int s_na2;                     // next active count
    __shared__ int s_cnt;                     // block0 edge counter

    const int t    = threadIdx.x;
    const int wid  = t >> 5;
    const int lane = t & 31;
    const int row  = blockIdx.x * 32 + wid;

    for (int i = t; i < NPTS; i += TPB) {
        comp[i] = (unsigned short)i;
        act[0][i] = (unsigned short)i;
    }
    if (t == 0) s_cnt = 0;
    __syncthreads();

    unsigned long long cache = g_cache[row];   // warp-uniform per-row best
    int na = NPTS;

    for (int k = 0; k < 12; k++) {
        const int p = k & 1;

        if (k > 0) {
            // ---- selection: cached edge if still out-of-comp, else rescan --
            const unsigned myc = comp[row];
            unsigned cj = (unsigned)(cache & 0xFFFFu);
            bool valid = (cache != ~0ull) && (comp[cj] != myc);
            if (!valid) {
                const float4*  r4  = (const float4*)(g_d2 + (size_t)row * NPTS);
                const ushort4* c4p = (const ushort4*)comp;
                unsigned long long best = ~0ull;
#pragma unroll 4
                for (int s = 0; s < 32; s++) {
                    const int q = s * 32 + lane;
                    float4  d  = r4[q];
                    ushort4 cc = c4p[q];
                    const unsigned col = (unsigned)(q * 4);
                    if (cc.x != myc)
                        best = umin64(best, ((unsigned long long)__float_as_uint(d.x) << 32) | (col + 0));
                    if (cc.y != myc)
                        best = umin64(best, ((unsigned long long)__float_as_uint(d.y) << 32) | (col + 1));
                    if (cc.z != myc)
                        best = umin64(best, ((unsigned long long)__float_as_uint(d.z) << 32) | (col + 2));
                    if (cc.w != myc)
                        best = umin64(best, ((unsigned long long)__float_as_uint(d.w) << 32) | (col + 3));
                }
#pragma unroll
                for (int s = 16; s > 0; s >>= 1)
                    best = umin64(best, __shfl_down_sync(0xFFFFFFFFu, best, s));
                cache = __shfl_sync(0xFFFFFFFFu, best, 0);
            }
            if (lane == 0 && cache != ~0ull)
                atomicMin(&g_best[k % 3][myc], cache2key(cache, (unsigned)row));
            gridbar();
        }

        // ---- hook over ACTIVE components (all blocks, redundant) ----
        const unsigned long long* B = g_best[k % 3];
        for (int idx = t; idx < na; idx += TPB) { int c = act[p][idx]; par[c] = c; }
        if (t == 0) s_na2 = 0;
        __syncthreads();

        for (int idx = t; idx < na; idx += TPB) {
            int c = act[p][idx];
            unsigned long long key =
                (k == 0) ? cache2key(g_cache[c], (unsigned)c) : B[c];
            bool isroot = false;
            if (key != ~0ull) {
                unsigned id = (unsigned)(key & 0xFFFFFFu);
                int u = (int)(id >> 12), v = (int)(id & 0xFFFu);
                int cu = comp[u], cv = comp[v];
                int other = (cu == c) ? cv : cu;
                unsigned long long okey =
                    (k == 0) ? cache2key(g_cache[other], (unsigned)other) : B[other];
                bool mutual = (okey == key);
                if (!mutual)        par[c] = other;
                else if (c > other) par[c] = other;
                else                isroot = true;
                if (blockIdx.x == 0 && (!mutual || c < other)) {
                    int e = atomicAdd(&s_cnt, 1);
                    g_len[e] = sqrtf(__uint_as_float((unsigned)(key >> 24)));
                }
            } else {
                isroot = true;
            }
            if (isroot) {
                int pos = atomicAdd(&s_na2, 1);
                act[p ^ 1][pos] = (unsigned short)c;
            }
        }
        __syncthreads();

        // pointer jumping over active list, early exit on convergence
        for (int it = 0; it < 12; it++) {
            int chg = 0;
            for (int idx = t; idx < na; idx += TPB) {
                int c = act[p][idx];
                int p1 = par[c];
                int p2 = par[p1];
                if (p2 != p1) { par[c] = p2; chg = 1; }
            }
            if (!__syncthreads_or(chg)) break;
        }

        // relabel all vertices + clear this block's slice of buffer (k+2)%3
        for (int i = t; i < NPTS; i += TPB)
            comp[i] = (unsigned short)par[comp[i]];
        if (t < 32) g_best[(k + 2) % 3][blockIdx.x * 32 + t] = ~0ull;
        __syncthreads();

        na = s_na2;
        if (na <= 1) break;
    }

    // ---- block 0: bitonic sort (pad one +inf), write output ----
    if (blockIdx.x != 0) return;
    __syncthreads();
    float* sh = (float*)par;
    for (int m = t; m < NPTS; m += TPB)
        sh[m] = (m < NPTS - 1) ? g_len[m] : inf32();
    __syncthreads();

    for (int kk = 2; kk <= NPTS; kk <<= 1) {
        for (int j = kk >> 1; j > 0; j >>= 1) {
#pragma unroll
            for (int tt = 0; tt < 2; tt++) {
                int u = t + tt * TPB;
                int i = ((u & ~(j - 1)) << 1) | (u & (j - 1));
                int l = i | j;
                float a = sh[i], c = sh[l];
                bool up = (i & kk) == 0;
                if ((a > c) == up) { sh[i] = c; sh[l] = a; }
            }
            __syncthreads();
        }
    }
    for (int m = t; m < NPTS - 1; m += TPB) out[m] = sh[m];
}

// ---------------------------------------------------------------------------
extern "C" void kernel_launch(void* const* d_in, const int* in_sizes, int n_in,
                              void* d_out, int out_size) {
    (void)in_sizes; (void)n_in; (void)out_size;
    const float* points = (const float*)d_in[0];
    float* out = (float*)d_out;

    k_init<<<NPTS * 32 / TPB, TPB>>>(points);            // 128 x 1024
    k_d2<<<dim3(NPTS / 128, NPTS / 128), 256>>>(points); // 32x32 x 256
    k_mst<<<NBLK, TPB>>>(out);
}

// round 10
// speedup vs baseline: 1.6617x; 1.0310x over previous
#include <cuda_runtime.h>
#include <cstdint>
#include <cstddef>

#define NPTS 4096
#define DIM  64
#define NBLK 128     // persistent blocks (<=148 SMs, 1 block/SM -> co-resident)
#define TPB  1024

// ---------------------------------------------------------------------------
// Scratch (allocation-free rule: __device__ globals)
// ---------------------------------------------------------------------------
__device__ float g_sq[NPTS];
__device__ float g_d2[(size_t)NPTS * NPTS];          // 64 MB f32, L2-resident
__device__ float g_len[NPTS];                        // MST edge lengths
__device__ unsigned long long g_bmin[NPTS * 32];     // 1 MB per-(row,128col) mins
__device__ unsigned long long g_best[3][NPTS];       // triple-buffered comp keys
__device__ int          g_bar_cnt;
__device__ volatile int g_bar_gen;

static __device__ __forceinline__ float inf32() { return __int_as_float(0x7f800000); }
static __device__ __forceinline__ unsigned long long umin64(unsigned long long a,
                                                            unsigned long long b) {
    return a < b ? a : b;
}
// global key = (f32 d2 bits << 24) | (min(u,v)<<12) | max(u,v)
// globally unique; identical from both endpoints => only mutual 2-cycles.
static __device__ __forceinline__ unsigned long long mkkey(unsigned wbits,
                                                           unsigned a, unsigned b) {
    unsigned lo = min(a, b), hi = max(a, b);
    return ((unsigned long long)wbits << 24) | (lo << 12) | hi;
}
// convert local row key (w<<32|j) of row c into the global canonical key
static __device__ __forceinline__ unsigned long long loc2key(unsigned long long ck,
                                                             unsigned c) {
    if (ck == ~0ull) return ~0ull;
    return mkkey((unsigned)(ck >> 32), c, (unsigned)(ck & 0xFFFFu));
}

static __device__ __forceinline__ void gridbar() {
    __syncthreads();
    if (threadIdx.x == 0) {
        __threadfence();
        int gen = g_bar_gen;
        if (atomicAdd(&g_bar_cnt, 1) == NBLK - 1) {
            g_bar_cnt = 0;
            __threadfence();
            g_bar_gen = gen + 1;
        } else {
            while (g_bar_gen == gen) { }
        }
        __threadfence();
    }
    __syncthreads();
}

// ---------------------------------------------------------------------------
// Kernel 1: warp-per-row squared norms + clear best buffers + barrier reset
// ---------------------------------------------------------------------------
__global__ void k_init(const float* __restrict__ p) {
    const int t   = threadIdx.x;
    const int gt  = blockIdx.x * TPB + t;
    const int row = gt >> 5;
    const int ln  = gt & 31;

    if (gt == 0) { g_bar_cnt = 0; g_bar_gen = 0; }
    if (gt < 3 * NPTS) ((unsigned long long*)g_best)[gt] = ~0ull;

    float2 v = *(const float2*)(p + (size_t)row * DIM + ln * 2);
    float acc = fmaf(v.x, v.x, v.y * v.y);
#pragma unroll
    for (int s = 16; s > 0; s >>= 1)
        acc += __shfl_down_sync(0xFFFFFFFFu, acc, s);
    if (ln == 0) g_sq[row] = acc;
}

// ---------------------------------------------------------------------------
// Kernel 2: f32 d2 matrix (128x128 tile, 8x8/thread, packed f32x2 FMA) with
// fused per-(row, col-block) min epilogue -> g_bmin[row*32 + jblk] (w<<32|j).
// ---------------------------------------------------------------------------
__global__ void k_d2(const float* __restrict__ p) {
    __shared__ float As[32][128];
    __shared__ float Bs[32][128];

    const int t  = threadIdx.x;          // 0..255
    const int tx = t & 15;
    const int ty = t >> 4;
    const int i0 = blockIdx.y * 128;
    const int j0 = blockIdx.x * 128;

    const int lr = t >> 1;
    const int lc = (t & 1) * 16;

    unsigned long long acc2[8][4];
#pragma unroll
    for (int m = 0; m < 8; m++)
#pragma unroll
        for (int n = 0; n < 4; n++) acc2[m][n] = 0ull;

#pragma unroll
    for (int k0 = 0; k0 < DIM; k0 += 32) {
#pragma unroll
        for (int q = 0; q < 4; q++) {
            int c = lc + q * 4;
            float4 va = *(const float4*)(p + (size_t)(i0 + lr) * DIM + k0 + c);
            As[c + 0][lr] = va.x; As[c + 1][lr] = va.y;
            As[c + 2][lr] = va.z; As[c + 3][lr] = va.w;
            float4 vb = *(const float4*)(p + (size_t)(j0 + lr) * DIM + k0 + c);
            Bs[c + 0][lr] = vb.x; Bs[c + 1][lr] = vb.y;
            Bs[c + 2][lr] = vb.z; Bs[c + 3][lr] = vb.w;
        }
        __syncthreads();

#pragma unroll
        for (int k = 0; k < 32; k++) {
            uint4 a0 = *(const uint4*)&As[k][ty * 8];
            uint4 a1 = *(const uint4*)&As[k][ty * 8 + 4];
            unsigned au[8] = {a0.x, a0.y, a0.z, a0.w, a1.x, a1.y, a1.z, a1.w};
            ulonglong2 b0 = *(const ulonglong2*)&Bs[k][tx * 8];
            ulonglong2 b1 = *(const ulonglong2*)&Bs[k][tx * 8 + 4];
            unsigned long long bp[4] = {b0.x, b0.y, b1.x, b1.y};
#pragma unroll
            for (int m = 0; m < 8; m++) {
                unsigned long long ap;
                asm("mov.b64 %0, {%1, %1};" : "=l"(ap) : "r"(au[m]));
#pragma unroll
                for (int n = 0; n < 4; n++)
                    asm("fma.rn.f32x2 %0, %1, %2, %0;"
                        : "+l"(acc2[m][n]) : "l"(ap), "l"(bp[n]));
            }
        }
        __syncthreads();
    }

    float sqi[8], sqj[8];
#pragma unroll
    for (int m = 0; m < 8; m++) sqi[m] = g_sq[i0 + ty * 8 + m];
#pragma unroll
    for (int n = 0; n < 8; n++) sqj[n] = g_sq[j0 + tx * 8 + n];

#pragma unroll
    for (int m = 0; m < 8; m++) {
        const int row = i0 + ty * 8 + m;
        float o[8];
#pragma unroll
        for (int n = 0; n < 4; n++) {
            unsigned lo, hi;
            asm("mov.b64 {%0, %1}, %2;" : "=r"(lo), "=r"(hi) : "l"(acc2[m][n]));
            float d0 = __uint_as_float(lo), d1 = __uint_as_float(hi);
            o[2 * n + 0] = fmaxf(sqi[m] + sqj[2 * n + 0] - 2.f * d0, 0.f);
            o[2 * n + 1] = fmaxf(sqi[m] + sqj[2 * n + 1] - 2.f * d1, 0.f);
        }
        float* dst = g_d2 + (size_t)row * NPTS + j0 + tx * 8;
        *(float4*)(dst)     = *(float4*)(o);
        *(float4*)(dst + 4) = *(float4*)(o + 4);

        // fused per-(row, 128-col block) min (w<<32|j), diag excluded
        unsigned long long key = ~0ull;
#pragma unroll
        for (int n = 0; n < 8; n++) {
            unsigned jj = (unsigned)(j0 + tx * 8 + n);
            if (jj != (unsigned)row)
                key = umin64(key, ((unsigned long long)__float_as_uint(o[n]) << 32) | jj);
        }
#pragma unroll
        for (int s = 8; s > 0; s >>= 1)
            key = umin64(key, __shfl_down_sync(0xFFFFFFFFu, key, s, 16));
        if (tx == 0) g_bmin[row * 32 + blockIdx.x] = key;
    }
}

// ---------------------------------------------------------------------------
// Kernel 3: persistent Boruvka + sort. Selection per warp/row via block-min
// bounds: lane l holds bmin of col-block l; cand = warp-min over entries with
// out-of-comp partner (exact edge); only blocks with bmin < cand and in-comp
// partner get a cooperative 128-entry scan. Exact == full-scan selection.
// One grid barrier per round; hook over active components, all blocks
// redundantly in their own shared memory.
// ---------------------------------------------------------------------------
__global__ void __launch_bounds__(TPB, 1) k_mst(float* __restrict__ out) {
    __shared__ unsigned short comp[NPTS];     // 8 KB persistent labels
    __shared__ int par[NPTS];                 // 16 KB; reused as float sort buf
    __shared__ unsigned short act[2][NPTS];   // 16 KB ping-pong active comps
    __shared__ int s_na2;                     // next active count
    __shared__ int s_cnt;                     // block0 edge counter

    const int t    = threadIdx.x;
    const int wid  = t >> 5;
    const int lane = t & 31;
    const int row  = blockIdx.x * 32 + wid;

    for (int i = t; i < NPTS; i += TPB) {
        comp[i] = (unsigned short)i;
        act[0][i] = (unsigned short)i;
    }
    if (t == 0) s_cnt = 0;
    __syncthreads();

    int na = NPTS;

    for (int k = 0; k < 12; k++) {
        const int p = k & 1;

        // ---- selection via block-min bounds ----
        {
            const unsigned myc = comp[row];
            unsigned long long e = g_bmin[row * 32 + lane];
            unsigned ej = (unsigned)(e & 0xFFFFu);
            bool oc = comp[ej] != myc;                 // partner out-of-comp?
            unsigned long long cand = oc ? e : ~0ull;
#pragma unroll
            for (int s = 16; s > 0; s >>= 1)
                cand = umin64(cand, __shfl_xor_sync(0xFFFFFFFFu, cand, s));

            unsigned scanmask = __ballot_sync(0xFFFFFFFFu, !oc && e < cand);
            unsigned long long best = cand;
            while (scanmask) {
                int b = __ffs(scanmask) - 1;
                scanmask &= scanmask - 1;
                const float* r = g_d2 + (size_t)row * NPTS + b * 128;
#pragma unroll
                for (int s2 = 0; s2 < 4; s2++) {
                    int jj = s2 * 32 + lane;
                    if (comp[b * 128 + jj] != myc) {
                        unsigned long long kk =
                            ((unsigned long long)__float_as_uint(r[jj]) << 32) |
                            (unsigned)(b * 128 + jj);
                        best = umin64(best, kk);
                    }
                }
            }
#pragma unroll
            for (int s = 16; s > 0; s >>= 1)
                best = umin64(best, __shfl_down_sync(0xFFFFFFFFu, best, s));
            if (lane == 0 && best != ~0ull)
                atomicMin(&g_best[k % 3][myc], loc2key(best, (unsigned)row));
        }
        gridbar();

        // ---- hook over ACTIVE components (all blocks, redundant) ----
        const unsigned long long* B = g_best[k % 3];
        for (int idx = t; idx < na; idx += TPB) { int c = act[p][idx]; par[c] = c; }
        if (t == 0) s_na2 = 0;
        __syncthreads();

        for (int idx = t; idx < na; idx += TPB) {
            int c = act[p][idx];
            unsigned long long key = B[c];
            bool isroot = false;
            if (key != ~0ull) {
                unsigned id = (unsigned)(key & 0xFFFFFFu);
                int u = (int)(id >> 12), v = (int)(id & 0xFFFu);
                int cu = comp[u], cv = comp[v];
                int other = (cu == c) ? cv : cu;
                bool mutual = (B[other] == key);
                if (!mutual)        par[c] = other;
                else if (c > other) par[c] = other;
                else                isroot = true;
                if (blockIdx.x == 0 && (!mutual || c < other)) {
                    int e = atomicAdd(&s_cnt, 1);
                    g_len[e] = sqrtf(__uint_as_float((unsigned)(key >> 24)));
                }
            } else {
                isroot = true;
            }
            if (isroot) {
                int pos = atomicAdd(&s_na2, 1);
                act[p ^ 1][pos] = (unsigned short)c;
            }
        }
        __syncthreads();

        // pointer jumping over active list, early exit on convergence
        for (int it = 0; it < 12; it++) {
            int chg = 0;
            for (int idx = t; idx < na; idx += TPB) {
                int c = act[p][idx];
                int p1 = par[c];
                int p2 = par[p1];
                if (p2 != p1) { par[c] = p2; chg = 1; }
            }
            if (!__syncthreads_or(chg)) break;
        }

        // relabel all vertices + clear this block's slice of buffer (k+2)%3
        for (int i = t; i < NPTS; i += TPB)
            comp[i] = (unsigned short)par[comp[i]];
        if (t < 32) g_best[(k + 2) % 3][blockIdx.x * 32 + t] = ~0ull;
        __syncthreads();

        na = s_na2;
        if (na <= 1) break;
    }

    // ---- block 0: bitonic sort (pad one +inf), write output ----
    if (blockIdx.x != 0) return;
    __syncthreads();
    float* sh = (float*)par;
    for (int m = t; m < NPTS; m += TPB)
        sh[m] = (m < NPTS - 1) ? g_len[m] : inf32();
    __syncthreads();

    for (int kk = 2; kk <= NPTS; kk <<= 1) {
        for (int j = kk >> 1; j > 0; j >>= 1) {
#pragma unroll
            for (int tt = 0; tt < 2; tt++) {
                int u = t + tt * TPB;
                int i = ((u & ~(j - 1)) << 1) | (u & (j - 1));
                int l = i | j;
                float a = sh[i], c = sh[l];
                bool up = (i & kk) == 0;
                if ((a > c) == up) { sh[i] = c; sh[l] = a; }
            }
            __syncthreads();
        }
    }
    for (int m = t; m < NPTS - 1; m += TPB) out[m] = sh[m];
}

// ---------------------------------------------------------------------------
extern "C" void kernel_launch(void* const* d_in, const int* in_sizes, int n_in,
                              void* d_out, int out_size) {
    (void)in_sizes; (void)n_in; (void)out_size;
    const float* points = (const float*)d_in[0];
    float* out = (float*)d_out;

    k_init<<<NPTS * 32 / TPB, TPB>>>(points);            // 128 x 1024
    k_d2<<<dim3(NPTS / 128, NPTS / 128), 256>>>(points); // 32x32 x 256
    k_mst<<<NBLK, TPB>>>(out);
}